// round 17
// baseline (speedup 1.0000x reference)
#include <cuda_runtime.h>
#include <cuda_fp16.h>
#include <math.h>
#include <stdint.h>

#define T_LEN 4096
#define DM 1024
#define NH 16
#define HD 64
#define WINDOW 1024
#define EPS_F 1e-6f
#define QSC 0.17312340490667564f   // 0.12 * log2(e)

// GEMM tiling: 128x128, BK=64, 128B rows, SW128 swizzle chunk^=row&7
// 2-term fp16: C = A*(Bhi+Blo); arrays: A, Bhi, Blo
#define BM 128
#define BN 128
#define BK 64
#define G_ARR 16384                 // 128 rows * 128 B
#define G_STAGE 49152               // 3 arrays
#define G_SMEM (2 * G_STAGE)        // 98304

// Attention: 128B rows, SW128 swizzle chunk^=row&7 (3-term fp16)
#define A_KARR 8192                 // 64 rows * 128 B
#define A_STAGE 32768               // Khi Klo Vhi Vlo
#define A_QARR 16384                // 128 rows * 128 B
#define A_SMEM (3 * A_STAGE)        // 98304

// ------------------------- scratch (no allocs allowed) ----------------------
__device__ float g_qkv[(size_t)T_LEN * 3 * DM];
__device__ __half g_x[(size_t)T_LEN * DM];
__device__ __half g_wqkv_hi[(size_t)3 * DM * DM];
__device__ __half g_wqkv_lo[(size_t)3 * DM * DM];
__device__ __half g_wo_hi[(size_t)DM * DM];
__device__ __half g_wo_lo[(size_t)DM * DM];
__device__ __half g_att[(size_t)T_LEN * DM];
__device__ __half g_qs_hi[(size_t)NH * T_LEN * HD];
__device__ __half g_qs_lo[(size_t)NH * T_LEN * HD];
__device__ __half g_ks_hi[(size_t)NH * T_LEN * HD];
__device__ __half g_ks_lo[(size_t)NH * T_LEN * HD];
__device__ __half g_vt_hi[(size_t)NH * HD * T_LEN];
__device__ __half g_vt_lo[(size_t)NH * HD * T_LEN];

// ------------------------- helpers ------------------------------------------
__device__ __forceinline__ uint32_t s2u(const void* p) {
    uint32_t a;
    asm("{ .reg .u64 t; cvta.to.shared.u64 t, %1; cvt.u32.u64 %0, t; }"
        : "=r"(a) : "l"(p));
    return a;
}
__device__ __forceinline__ void cpa16(uint32_t dst, const void* src) {
    asm volatile("cp.async.cg.shared.global [%0], [%1], 16;" :: "r"(dst), "l"(src));
}
#define CP_COMMIT() asm volatile("cp.async.commit_group;" ::: "memory")
#define CP_WAIT(n)  asm volatile("cp.async.wait_group %0;" :: "n"(n) : "memory")
__device__ __forceinline__ void ldsm_x4(uint32_t& r0, uint32_t& r1,
                                        uint32_t& r2, uint32_t& r3, uint32_t a) {
    asm volatile("ldmatrix.sync.aligned.m8n8.x4.shared.b16 {%0,%1,%2,%3}, [%4];"
                 : "=r"(r0), "=r"(r1), "=r"(r2), "=r"(r3) : "r"(a));
}
__device__ __forceinline__ void mma16816(float* c, const uint32_t* a,
                                         uint32_t b0, uint32_t b1) {
    asm volatile(
        "mma.sync.aligned.m16n8k16.row.col.f32.f16.f16.f32 "
        "{%0,%1,%2,%3}, {%4,%5,%6,%7}, {%8,%9}, {%0,%1,%2,%3};"
        : "+f"(c[0]), "+f"(c[1]), "+f"(c[2]), "+f"(c[3])
        : "r"(a[0]), "r"(a[1]), "r"(a[2]), "r"(a[3]), "r"(b0), "r"(b1));
}
__device__ __forceinline__ float fex2(float x) {
    float y;
    asm("ex2.approx.ftz.f32 %0, %1;" : "=f"(y) : "f"(x));
    return y;
}
__device__ __forceinline__ uint32_t packh2(float a, float b) {
    __half2 p = __halves2half2(__float2half(a), __float2half(b));
    return *(uint32_t*)&p;
}
__device__ __forceinline__ void packpl(float p0, float p1, uint32_t& hi, uint32_t& lo) {
    __half h0 = __float2half(p0), h1 = __float2half(p1);
    __half2 hp = __halves2half2(h0, h1);
    hi = *(uint32_t*)&hp;
    __half2 lp = __halves2half2(__float2half(p0 - __half2float(h0)),
                                __float2half(p1 - __half2float(h1)));
    lo = *(uint32_t*)&lp;
}

// ---------------------------------------------------------------------------
// fp32 -> fp16 (1-term, for x)
// ---------------------------------------------------------------------------
__global__ __launch_bounds__(256) void cvt_h1(const float* __restrict__ in,
                                              __half* __restrict__ out, int n4)
{
    int i = blockIdx.x * 256 + threadIdx.x;
    if (i >= n4) return;
    float4 v = ((const float4*)in)[i];
    ((uint32_t*)out)[2 * i]     = packh2(v.x, v.y);
    ((uint32_t*)out)[2 * i + 1] = packh2(v.z, v.w);
}

// fp32 -> (fp16 hi, fp16 lo) split (for weights)
__global__ __launch_bounds__(256) void cvt_h2(const float* __restrict__ in,
                                              __half* __restrict__ hi,
                                              __half* __restrict__ lo, int n4)
{
    int i = blockIdx.x * 256 + threadIdx.x;
    if (i >= n4) return;
    float4 v = ((const float4*)in)[i];
    uint32_t h0, l0, h1, l1;
    packpl(v.x, v.y, h0, l0);
    packpl(v.z, v.w, h1, l1);
    ((uint32_t*)hi)[2 * i]     = h0;
    ((uint32_t*)hi)[2 * i + 1] = h1;
    ((uint32_t*)lo)[2 * i]     = l0;
    ((uint32_t*)lo)[2 * i + 1] = l1;
}

// ---------------------------------------------------------------------------
// mma.sync GEMM: C = A @ (Bhi+Blo)^T, fp16 2-term. BK=64, 2-stage pipeline,
// one sync per K-iter, SW128 smem, term-major, 2 CTAs/SM.
// ---------------------------------------------------------------------------
extern __shared__ __align__(128) char gsm[];

__global__ __launch_bounds__(256, 2) void gemm_mma(const __half* __restrict__ A,
                                                   const __half* __restrict__ Bhi,
                                                   const __half* __restrict__ Blo,
                                                   float* __restrict__ C,
                                                   int M, int N, int K)
{
    uint32_t sbase = s2u(gsm);
    int tid = threadIdx.x;
    int wid = tid >> 5;
    int lane = tid & 31;
    int wm = (wid >> 2) * 64;
    int wn = (wid & 3) * 32;
    int row0 = blockIdx.y * BM;
    int col0 = blockIdx.x * BN;

    // loader: thread -> row (tid>>1), 4 consecutive 16B chunks (tid&1)*4..+3
    int lrow = tid >> 1;
    int lk4 = (tid & 1) * 4;
    const char* gA  = (const char*)(A   + (size_t)(row0 + lrow) * K + lk4 * 8);
    const char* gBh = (const char*)(Bhi + (size_t)(col0 + lrow) * K + lk4 * 8);
    const char* gBl = (const char*)(Blo + (size_t)(col0 + lrow) * K + lk4 * 8);
    uint32_t swc[4];
    {
        uint32_t swrow = lrow & 7;
#pragma unroll
        for (int c = 0; c < 4; c++)
            swc[c] = (uint32_t)lrow * 128 + (((uint32_t)(lk4 + c) ^ swrow) << 4);
    }

#define LOAD_STAGE(st, k0)                                                  \
    do {                                                                    \
        uint32_t sb = sbase + (st) * G_STAGE;                               \
        size_t go = (size_t)(k0) * 2;                                       \
        _Pragma("unroll")                                                   \
        for (int c = 0; c < 4; c++) {                                       \
            cpa16(sb + swc[c],             gA  + go + c * 16);              \
            cpa16(sb + G_ARR + swc[c],     gBh + go + c * 16);              \
            cpa16(sb + 2 * G_ARR + swc[c], gBl + go + c * 16);              \
        }                                                                   \
    } while (0)

    float acc[4][4][4] = {};

    int a_r = wm + (lane & 15);
    int b_r = wn + ((lane >> 4) << 3) + (lane & 7);
    uint32_t srow = lane & 7;            // row&7 for both A and B lane addrs
    uint32_t a_cb = lane >> 4;
    uint32_t b_cb = (lane >> 3) & 1;

    LOAD_STAGE(0, 0);
    CP_COMMIT();

    const int NKT = K / BK;              // 16
    for (int kt = 0; kt < NKT; kt++) {
        CP_WAIT(0);
        __syncthreads();
        if (kt + 1 < NKT) {
            LOAD_STAGE((kt + 1) & 1, (kt + 1) * BK);
            CP_COMMIT();
        }

        uint32_t stb = sbase + (kt & 1) * G_STAGE;
#pragma unroll
        for (int ks = 0; ks < 4; ks++) {
            uint32_t ah[4][4];
            uint32_t acsw = (((uint32_t)(ks * 2) + a_cb) ^ srow) << 4;
#pragma unroll
            for (int mt = 0; mt < 4; mt++) {
                uint32_t aaddr = stb + (a_r + mt * 16) * 128 + acsw;
                ldsm_x4(ah[mt][0], ah[mt][1], ah[mt][2], ah[mt][3], aaddr);
            }
            uint32_t bcsw = (((uint32_t)(ks * 2) + b_cb) ^ srow) << 4;
#pragma unroll
            for (int nt2 = 0; nt2 < 2; nt2++) {
                uint32_t bh[4], bl[4];
                uint32_t baddr = stb + G_ARR + (b_r + nt2 * 16) * 128 + bcsw;
                ldsm_x4(bh[0], bh[1], bh[2], bh[3], baddr);
                ldsm_x4(bl[0], bl[1], bl[2], bl[3], baddr + G_ARR);
                // term A*Bhi
#pragma unroll
                for (int mt = 0; mt < 4; mt++) {
                    mma16816(acc[mt][2 * nt2],     ah[mt], bh[0], bh[1]);
                    mma16816(acc[mt][2 * nt2 + 1], ah[mt], bh[2], bh[3]);
                }
                // term A*Blo
#pragma unroll
                for (int mt = 0; mt < 4; mt++) {
                    mma16816(acc[mt][2 * nt2],     ah[mt], bl[0], bl[1]);
                    mma16816(acc[mt][2 * nt2 + 1], ah[mt], bl[2], bl[3]);
                }
            }
        }
    }
#undef LOAD_STAGE

    int erow = row0 + wm + (lane >> 2);
    int ecol0 = col0 + wn + (lane & 3) * 2;
#pragma unroll
    for (int mt = 0; mt < 4; mt++) {
#pragma unroll
        for (int nt = 0; nt < 4; nt++) {
            float* c = acc[mt][nt];
            size_t r0i = (size_t)(erow + mt * 16) * N + ecol0 + nt * 8;
            *(float2*)&C[r0i]         = make_float2(c[0], c[1]);
            *(float2*)&C[r0i + 8 * N] = make_float2(c[2], c[3]);
        }
    }
}

// ---------------------------------------------------------------------------
// qkv_prep: RMSNorm q,k + RoPE + v*0.5, fp16 hi/lo outputs
// ---------------------------------------------------------------------------
__global__ __launch_bounds__(256) void qkv_prep(const float* __restrict__ qw,
                                                const float* __restrict__ kw,
                                                const float* __restrict__ cosb,
                                                const float* __restrict__ sinb)
{
    __shared__ float vt_s[64][33];
    int tid = threadIdx.x;
    int wid = tid >> 5, lane = tid & 31;
    int h = blockIdx.y;
    int t0 = blockIdx.x * 32;

#pragma unroll
    for (int j = 0; j < 4; j++) {
        int tl = wid * 4 + j;
        int t = t0 + tl;
        const float* rowbase = g_qkv + (size_t)t * (3 * DM) + h * HD;
        float2 qv = ((const float2*)rowbase)[lane];
        float2 kv = ((const float2*)(rowbase + DM))[lane];
        float2 vv = ((const float2*)(rowbase + 2 * DM))[lane];

        float sq = qv.x * qv.x + qv.y * qv.y;
        float sk = kv.x * kv.x + kv.y * kv.y;
#pragma unroll
        for (int off = 16; off; off >>= 1) {
            sq += __shfl_xor_sync(0xffffffffu, sq, off);
            sk += __shfl_xor_sync(0xffffffffu, sk, off);
        }
        float rq = rsqrtf(sq * (1.f / 64.f) + EPS_F);
        float rk = rsqrtf(sk * (1.f / 64.f) + EPS_F);

        int d0 = lane * 2;
        float q0 = qv.x * rq * qw[d0], q1 = qv.y * rq * qw[d0 + 1];
        float k0 = kv.x * rk * kw[d0], k1 = kv.y * rk * kw[d0 + 1];

        if (lane < 16) {
            float c = cosb[t * 16 + lane];
            float s = sinb[t * 16 + lane];
            float e = q0, o = q1;
            q0 = e * c - o * s;  q1 = e * s + o * c;
            e = k0; o = k1;
            k0 = e * c - o * s;  k1 = e * s + o * c;
        }
        q0 *= QSC; q1 *= QSC;

        size_t base = ((size_t)h * T_LEN + t) * HD + d0;
        uint32_t ph, pl;
        packpl(q0, q1, ph, pl);
        *(uint32_t*)&g_qs_hi[base] = ph;
        *(uint32_t*)&g_qs_lo[base] = pl;
        packpl(k0, k1, ph, pl);
        *(uint32_t*)&g_ks_hi[base] = ph;
        *(uint32_t*)&g_ks_lo[base] = pl;

        vt_s[d0][tl]     = vv.x * 0.5f;
        vt_s[d0 + 1][tl] = vv.y * 0.5f;
    }
    __syncthreads();

    int d = tid >> 2;
    int tg = (tid & 3) * 8;
    uint32_t hi[4], lo[4];
#pragma unroll
    for (int i = 0; i < 4; i++) {
        float a = vt_s[d][tg + 2 * i], b = vt_s[d][tg + 2 * i + 1];
        packpl(a, b, hi[i], lo[i]);
    }
    size_t vbase = ((size_t)h * HD + d) * T_LEN + t0 + tg;
    *(uint4*)&g_vt_hi[vbase] = make_uint4(hi[0], hi[1], hi[2], hi[3]);
    *(uint4*)&g_vt_lo[vbase] = make_uint4(lo[0], lo[1], lo[2], lo[3]);
}

// ---------------------------------------------------------------------------
// Tensor-core flash attention: fp16 3-term, 3-region smem ring, 2 CTAs/SM.
// 1D grid ordered heavy-blocks-first for wave balance.
// ---------------------------------------------------------------------------
__device__ __forceinline__ void attn_load_chunk(uint32_t dstbase, int s0,
                                                int h, int tid)
{
    int arr = tid >> 6, r = tid & 63;
    uint32_t dst = dstbase + arr * A_KARR + r * 128;
    uint32_t sw = r & 7;
    const __half* src;
    if (arr == 0)      src = g_ks_hi + ((size_t)h * T_LEN + s0 + r) * HD;
    else if (arr == 1) src = g_ks_lo + ((size_t)h * T_LEN + s0 + r) * HD;
    else if (arr == 2) src = g_vt_hi + ((size_t)h * HD + r) * T_LEN + s0;
    else               src = g_vt_lo + ((size_t)h * HD + r) * T_LEN + s0;
#pragma unroll
    for (int c = 0; c < 8; c++)
        cpa16(dst + (((uint32_t)c ^ sw) << 4), (const char*)src + c * 16);
}

__global__ __launch_bounds__(256, 2) void attn_mma()
{
    uint32_t sb0 = s2u(gsm);
    int tid = threadIdx.x;
    int wid = tid >> 5, lane = tid & 31;
    // heavy-first mapping: high q0 (more chunks) gets low blockIdx
    int h = blockIdx.x & 15;
    int q0 = (31 - (blockIdx.x >> 4)) * 128;

    // Q -> region 0 (hi at 0, lo at +A_QARR), SW128
    {
        int arr = tid >> 7, r = tid & 127;
        const __half* src = (arr ? g_qs_lo : g_qs_hi) +
                            ((size_t)h * T_LEN + q0 + r) * HD;
        uint32_t dst = sb0 + arr * A_QARR + r * 128;
        uint32_t sw = r & 7;
#pragma unroll
        for (int c = 0; c < 8; c++)
            cpa16(dst + (((uint32_t)c ^ sw) << 4), (const char*)src + c * 16);
    }

    int s_begin = (q0 >= WINDOW) ? q0 - WINDOW : 0;
    int nch = (q0 + 64 - s_begin) / 64 + 1;

    attn_load_chunk(sb0 + A_STAGE, s_begin, h, tid);
    CP_COMMIT();
    attn_load_chunk(sb0 + 2 * A_STAGE, s_begin + 64, h, tid);
    CP_COMMIT();

    int ldsB_r = ((lane >> 4) << 3) + (lane & 7);
    uint32_t ssw = lane & 7;
    uint32_t cbit = (lane >> 3) & 1;
    int qlo_row = q0 + wid * 16 + (lane >> 2);

    CP_WAIT(1);
    __syncthreads();

    uint32_t qh[4][4], ql[4][4];
    {
        int qrow = wid * 16 + (lane & 15);
        uint32_t qbase = sb0 + qrow * 128;
        uint32_t qsw = qrow & 7;
#pragma unroll
        for (int kd = 0; kd < 4; kd++) {
            uint32_t qa = qbase + ((((uint32_t)(kd * 2) + (lane >> 4)) ^ qsw) << 4);
            ldsm_x4(qh[kd][0], qh[kd][1], qh[kd][2], qh[kd][3], qa);
            ldsm_x4(ql[kd][0], ql[kd][1], ql[kd][2], ql[kd][3], qa + A_QARR);
        }
    }

    float m0 = -1e30f, m1 = -1e30f, l0 = 0.f, l1 = 0.f;
    float O[8][4] = {};

    for (int i = 0; i < nch; i++) {
        int s0 = s_begin + i * 64;
        uint32_t stb = sb0 + ((i + 1) % 3) * A_STAGE;
        CP_WAIT(1);
        __syncthreads();
        if (i + 2 < nch)
            attn_load_chunk(sb0 + ((i + 3) % 3) * A_STAGE, s0 + 128, h, tid);
        CP_COMMIT();

        // ---- S = Q @ K^T (term-major 3-term) ----
        float S[8][4] = {};
#pragma unroll
        for (int kd = 0; kd < 4; kd++) {
            uint32_t kcsw = (((uint32_t)(kd * 2) + cbit) ^ ssw) << 4;
#pragma unroll
            for (int p = 0; p < 2; p++) {
                uint32_t bh[2][4], bl[2][4];
#pragma unroll
                for (int j = 0; j < 2; j++) {
                    uint32_t ka = stb + ((2 * p + j) * 16 + ldsB_r) * 128 + kcsw;
                    ldsm_x4(bh[j][0], bh[j][1], bh[j][2], bh[j][3], ka);
                    ldsm_x4(bl[j][0], bl[j][1], bl[j][2], bl[j][3], ka + A_KARR);
                }
#pragma unroll
                for (int j = 0; j < 2; j++) {
                    mma16816(S[2 * (2 * p + j)],     qh[kd], bh[j][0], bh[j][1]);
                    mma16816(S[2 * (2 * p + j) + 1], qh[kd], bh[j][2], bh[j][3]);
                }
#pragma unroll
                for (int j = 0; j < 2; j++) {
                    mma16816(S[2 * (2 * p + j)],     qh[kd], bl[j][0], bl[j][1]);
                    mma16816(S[2 * (2 * p + j) + 1], qh[kd], bl[j][2], bl[j][3]);
                }
#pragma unroll
                for (int j = 0; j < 2; j++) {
                    mma16816(S[2 * (2 * p + j)],     ql[kd], bh[j][0], bh[j][1]);
                    mma16816(S[2 * (2 * p + j) + 1], ql[kd], bh[j][2], bh[j][3]);
                }
            }
        }

        // ---- mask (boundary chunks only) ----
        if ((s0 + 63 > q0) || (q0 + 127 - s0 >= WINDOW)) {
#pragma unroll
            for (int nt = 0; nt < 8; nt++) {
                int sc = s0 + nt * 8 + (lane & 3) * 2;
#pragma unroll
                for (int e = 0; e < 2; e++) {
                    int d1 = qlo_row - (sc + e);
                    int d2 = d1 + 8;
                    if (d1 < 0 || d1 >= WINDOW) S[nt][e] = -1e30f;
                    if (d2 < 0 || d2 >= WINDOW) S[nt][2 + e] = -1e30f;
                }
            }
        }

        // ---- online softmax (log2 space) ----
        float r0 = -1e30f, r1 = -1e30f;
#pragma unroll
        for (int nt = 0; nt < 8; nt++) {
            r0 = fmaxf(r0, fmaxf(S[nt][0], S[nt][1]));
            r1 = fmaxf(r1, fmaxf(S[nt][2], S[nt][3]));
        }
        r0 = fmaxf(r0, __shfl_xor_sync(0xffffffffu, r0, 1));
        r0 = fmaxf(r0, __shfl_xor_sync(0xffffffffu, r0, 2));
        r1 = fmaxf(r1, __shfl_xor_sync(0xffffffffu, r1, 1));
        r1 = fmaxf(r1, __shfl_xor_sync(0xffffffffu, r1, 2));
        float mn0 = fmaxf(m0, r0), mn1 = fmaxf(m1, r1);
        float al0 = fex2(m0 - mn0), al1 = fex2(m1 - mn1);
        m0 = mn0; m1 = mn1;
        float ps0 = 0.f, ps1 = 0.f;
#pragma unroll
        for (int nt = 0; nt < 8; nt++) {
            S[nt][0] = fex2(S[nt][0] - mn0);
            S[nt][1] = fex2(S[nt][1] - mn0);
            S[nt][2] = fex2(S[nt][2] - mn1);
            S[nt][3] = fex2(S[nt][3] - mn1);
            ps0 += S[nt][0] + S[nt][1];
            ps1 += S[nt][2] + S[nt][3];
        }
        ps0 += __shfl_xor_sync(0xffffffffu, ps0, 1);
        ps0 += __shfl_xor_sync(0xffffffffu, ps0, 2);
        ps1 += __shfl_xor_sync(0xffffffffu, ps1, 1);
        ps1 += __shfl_xor_sync(0xffffffffu, ps1, 2);
        l0 = l0 * al0 + ps0;
        l1 = l1 * al1 + ps1;
#pragma unroll
        for (int nt = 0; nt < 8; nt++) {
            O[nt][0] *= al0; O[nt][1] *= al0;
            O[nt][2] *= al1; O[nt][3] *= al1;
        }

        // ---- O += P @ V (term-major 3-term; P split exactly) ----
#pragma unroll
        for (int kc = 0; kc < 4; kc++) {
            uint32_t pa[4], pl[4];
            packpl(S[2 * kc][0],     S[2 * kc][1],     pa[0], pl[0]);
            packpl(S[2 * kc][2],     S[2 * kc][3],     pa[1], pl[1]);
            packpl(S[2 * kc + 1][0], S[2 * kc + 1][1], pa[2], pl[2]);
            packpl(S[2 * kc + 1][2], S[2 * kc + 1][3], pa[3], pl[3]);
            uint32_t vcsw = (((uint32_t)(kc * 2) + cbit) ^ ssw) << 4;
#pragma unroll
            for (int p = 0; p < 2; p++) {
                uint32_t vh[2][4], vl[2][4];
#pragma unroll
                for (int j = 0; j < 2; j++) {
                    uint32_t va = stb + 2 * A_KARR +
                                  ((2 * p + j) * 16 + ldsB_r) * 128 + vcsw;
                    ldsm_x4(vh[j][0], vh[j][1], vh[j][2], vh[j][3], va);
                    ldsm_x4(vl[j][0], vl[j][1], vl[j][2], vl[j][3], va + A_KARR);
                }
#pragma unroll
                for (int j = 0; j < 2; j++) {
                    mma16816(O[2 * (2 * p + j)],     pa, vh[j][0], vh[j][1]);
                    mma16816(O[2 * (2 * p + j) + 1], pa, vh[j][2], vh[j][3]);
                }
#pragma unroll
                for (int j = 0; j < 2; j++) {
                    mma16816(O[2 * (2 * p + j)],     pa, vl[j][0], vl[j][1]);
                    mma16816(O[2 * (2 * p + j) + 1], pa, vl[j][2], vl[j][3]);
                }
#pragma unroll
                for (int j = 0; j < 2; j++) {
                    mma16816(O[2 * (2 * p + j)],     pl, vh[j][0], vh[j][1]);
                    mma16816(O[2 * (2 * p + j) + 1], pl, vh[j][2], vh[j][3]);
                }
            }
        }
    }

    // ---- epilogue: normalize, write att as fp16 (gemm2 A operand) ----
    float i0 = 1.f / l0, i1 = 1.f / l1;
    int colb = h * HD + (lane & 3) * 2;
#pragma unroll
    for (int nt = 0; nt < 8; nt++) {
        size_t b0 = (size_t)qlo_row * DM + colb + nt * 8;
        size_t b1 = (size_t)(qlo_row + 8) * DM + colb + nt * 8;
        *(uint32_t*)&g_att[b0] = packh2(O[nt][0] * i0, O[nt][1] * i0);
        *(uint32_t*)&g_att[b1] = packh2(O[nt][2] * i1, O[nt][3] * i1);
    }
}

// ---------------------------------------------------------------------------
extern "C" void kernel_launch(void* const* d_in, const int* in_sizes, int n_in,
                              void* d_out, int out_size)
{
    const float* x     = (const float*)d_in[0];
    const float* w_qkv = (const float*)d_in[3];
    const float* w_o   = (const float*)d_in[4];
    const float* qw    = (const float*)d_in[5];
    const float* kw    = (const float*)d_in[6];
    const float* cosb  = (const float*)d_in[7];
    const float* sinb  = (const float*)d_in[8];
    float* out = (float*)d_out;

    float* qkv_p = nullptr;
    __half *xp, *wqh, *wql, *woh, *wol, *atp;
    cudaGetSymbolAddress((void**)&qkv_p, g_qkv);
    cudaGetSymbolAddress((void**)&xp, g_x);
    cudaGetSymbolAddress((void**)&wqh, g_wqkv_hi);
    cudaGetSymbolAddress((void**)&wql, g_wqkv_lo);
    cudaGetSymbolAddress((void**)&woh, g_wo_hi);
    cudaGetSymbolAddress((void**)&wol, g_wo_lo);
    cudaGetSymbolAddress((void**)&atp, g_att);

    static bool attr_done = false;
    if (!attr_done) {
        cudaFuncSetAttribute(gemm_mma, cudaFuncAttributeMaxDynamicSharedMemorySize, G_SMEM);
        cudaFuncSetAttribute(attn_mma, cudaFuncAttributeMaxDynamicSharedMemorySize, A_SMEM);
        attr_done = true;
    }

    // 0) converts
    cvt_h1<<<(T_LEN * DM / 4 + 255) / 256, 256>>>(x, xp, T_LEN * DM / 4);
    cvt_h2<<<(3 * DM * DM / 4 + 255) / 256, 256>>>(w_qkv, wqh, wql, 3 * DM * DM / 4);
    cvt_h2<<<(DM * DM / 4 + 255) / 256, 256>>>(w_o, woh, wol, DM * DM / 4);

    // 1) qkv = x @ w_qkv^T  (fp16 2-term)
    dim3 g1(3 * DM / BN, T_LEN / BM);
    gemm_mma<<<g1, 256, G_SMEM>>>(xp, wqh, wql, qkv_p, T_LEN, 3 * DM, DM);

    // 2) norm + rope + v-scale, emit fp16 hi/lo
    dim3 gp(T_LEN / 32, NH);
    qkv_prep<<<gp, 256>>>(qw, kw, cosb, sinb);

    // 3) tensor-core windowed attention -> att (fp16), heavy-first 1D grid
    attn_mma<<<(T_LEN / 128) * NH, 256, A_SMEM>>>();

    // 4) out = att @ w_o^T  (fp16 2-term)
    dim3 g2(DM / BN, T_LEN / BM);
    gemm_mma<<<g2, 256, G_SMEM>>>(atp, woh, wol, out, T_LEN, DM, DM);
}